// round 2
// baseline (speedup 1.0000x reference)
#include <cuda_runtime.h>

// ADI diffusion: 10 steps of [channel-mix, x half-step, y full-step, x half-step].
// B=16, C=8, S=128. All solves are length-128 Thomas tridiagonal solves with
// per-element coefficients clip(base + t*tc, 1e-6, 10) * scale.
//
// Design:
//  - Everything staged through padded shared memory (pitch 129 -> bank-conflict
//    free for both row-oriented and column-oriented line solves).
//  - x kernels: block = (batch b, 16-row h-tile) owning all 8 channels
//    -> channel mixing is block-local, so [x-half | mix | x-half] fuses.
//  - y kernel: block = (b, c) full 128x128 plane, thread-per-column solve.
//  - 21 kernel launches total, all in-place on d_out (d_out is the working
//    state buffer; first kernel reads the input u).

#define S_DIM 128
#define C_DIM 8
#define B_DIM 16
#define PITCH 129
#define PLANE (S_DIM * PITCH)
#define NTHREADS 128
#define EPSF 1e-6f

// Sequential Thomas solve of one length-128 line living in shared memory.
//   d   : rhs in, solution out (in place)
//   cs  : scratch for c* coefficients
//   co  : per-element coefficient (already scaled: alpha*half/dx^2 etc.)
// System: a_i = -co_i, c_i = -co_i, b_i = 1+2co_i (ends: 1+co_i),
// denom_i = b_i - a_i*cs_{i-1} + EPS  (matches reference exactly).
__device__ __forceinline__ void thomas_line(float* __restrict__ d,
                                            float* __restrict__ cs,
                                            const float* __restrict__ co,
                                            int base, int stride) {
    // i = 0
    float c0 = co[base];
    float den = (1.0f + c0) + EPSF;
    float inv = __fdividef(1.0f, den);
    float csv = -c0 * inv;
    float dsv = d[base] * inv;
    cs[base] = csv;
    d[base] = dsv;
    for (int i = 1; i < S_DIM; i++) {
        int idx = base + i * stride;
        float ci = co[idx];
        float bv = (i == S_DIM - 1) ? (1.0f + ci) : (1.0f + 2.0f * ci);
        // denom = b - a*cs_prev + eps ; a = -ci  ->  b + ci*cs_prev + eps
        float deni = fmaf(ci, csv, bv) + EPSF;
        float invi = __fdividef(1.0f, deni);
        csv = -ci * invi;
        // ds = (d - a*ds_prev)/den = (d + ci*ds_prev)*inv
        dsv = fmaf(ci, dsv, d[idx]) * invi;
        cs[idx] = csv;
        d[idx] = dsv;
    }
    // backward substitution: x_{N-1} = ds_{N-1}; x_i = ds_i - cs_i*x_{i+1}
    float x = dsv;  // already stored at last position
    for (int i = S_DIM - 2; i >= 0; i--) {
        int idx = base + i * stride;
        x = fmaf(-cs[idx], x, d[idx]);
        d[idx] = x;
    }
}

// Stage alpha/beta coefficient tile into sC (scaled, clipped at time t).
// Lines are (c*16 + hh) rows of the h-tile for x kernels.
__device__ __forceinline__ void stage_coeff_x(float* __restrict__ sC,
                                              const float* __restrict__ cb,
                                              const float* __restrict__ ct,
                                              int h0, float t, float scale) {
    int tid = threadIdx.x;
    for (int idx = tid; idx < S_DIM * S_DIM; idx += NTHREADS) {
        int line = idx >> 7, w = idx & 127;
        int c = line >> 4, hh = line & 15;
        int g = (c * S_DIM + (h0 + hh)) * S_DIM + w;
        float v = fmaf(ct[g], t, cb[g]);
        v = fminf(fmaxf(v, EPSF), 10.0f);
        sC[line * PITCH + w] = v * scale;
    }
}

__device__ __forceinline__ void stage_u_x(float* __restrict__ sU,
                                          const float* __restrict__ g,
                                          int b, int h0) {
    int tid = threadIdx.x;
    for (int idx = tid; idx < S_DIM * S_DIM; idx += NTHREADS) {
        int line = idx >> 7, w = idx & 127;
        int c = line >> 4, hh = line & 15;
        sU[line * PITCH + w] =
            g[(((b * C_DIM + c) * S_DIM) + (h0 + hh)) * S_DIM + w];
    }
}

__device__ __forceinline__ void store_u_x(const float* __restrict__ sU,
                                          float* __restrict__ g,
                                          int b, int h0) {
    int tid = threadIdx.x;
    for (int idx = tid; idx < S_DIM * S_DIM; idx += NTHREADS) {
        int line = idx >> 7, w = idx & 127;
        int c = line >> 4, hh = line & 15;
        g[(((b * C_DIM + c) * S_DIM) + (h0 + hh)) * S_DIM + w] =
            sU[line * PITCH + w];
    }
}

// Channel mixing inside an x-tile: dst[(d,hh)] = sum_c M[d][c] * src[(c,hh)].
__device__ __forceinline__ void mix_tile(const float* __restrict__ src,
                                         float* __restrict__ dst,
                                         const float* __restrict__ sM) {
    int tid = threadIdx.x;
    int dch = tid >> 4, hh = tid & 15;
    float m[8];
#pragma unroll
    for (int c = 0; c < 8; c++) m[c] = sM[dch * 8 + c];
    int dst_base = (dch * 16 + hh) * PITCH;
    for (int w = 0; w < S_DIM; w++) {
        float acc = 0.0f;
#pragma unroll
        for (int c = 0; c < 8; c++)
            acc = fmaf(m[c], src[(c * 16 + hh) * PITCH + w], acc);
        dst[dst_base + w] = acc;
    }
}

// ---------------- Kernels ----------------

// First phase: channel-mix + x half-step. Reads u_in, writes u_out.
__global__ void k_mix_x(const float* __restrict__ u_in,
                        const float* __restrict__ M,
                        const float* __restrict__ ab,
                        const float* __restrict__ atc,
                        float* __restrict__ u_out, float t) {
    extern __shared__ float sm[];
    float* sP0 = sm;
    float* sP1 = sm + PLANE;
    float* sP2 = sm + 2 * PLANE;
    float* sM = sm + 3 * PLANE;
    int tid = threadIdx.x, b = blockIdx.x, h0 = blockIdx.y * 16;
    if (tid < 64) sM[tid] = M[tid];
    stage_u_x(sP1, u_in, b, h0);
    stage_coeff_x(sP2, ab, atc, h0, t, 0.0005f);  // half/DX^2
    __syncthreads();
    mix_tile(sP1, sP0, sM);
    __syncthreads();
    thomas_line(sP0, sP1, sP2, tid * PITCH, 1);
    __syncthreads();
    store_u_x(sP0, u_out, b, h0);
}

// Fused: x half-step (end of step k) + mix + x half-step (start of step k+1).
// Both solves use alpha evaluated at the SAME t -> one coeff stage. In place.
__global__ void k_x_mix_x(float* __restrict__ u,
                          const float* __restrict__ M,
                          const float* __restrict__ ab,
                          const float* __restrict__ atc, float t) {
    extern __shared__ float sm[];
    float* sP0 = sm;
    float* sP1 = sm + PLANE;
    float* sP2 = sm + 2 * PLANE;
    float* sM = sm + 3 * PLANE;
    int tid = threadIdx.x, b = blockIdx.x, h0 = blockIdx.y * 16;
    if (tid < 64) sM[tid] = M[tid];
    stage_u_x(sP0, u, b, h0);
    stage_coeff_x(sP2, ab, atc, h0, t, 0.0005f);
    __syncthreads();
    thomas_line(sP0, sP1, sP2, tid * PITCH, 1);  // trailing x of step k
    __syncthreads();
    mix_tile(sP0, sP1, sM);
    __syncthreads();
    thomas_line(sP1, sP0, sP2, tid * PITCH, 1);  // leading x of step k+1
    __syncthreads();
    store_u_x(sP1, u, b, h0);
}

// Final trailing x half-step of the last step. In place.
__global__ void k_x(float* __restrict__ u,
                    const float* __restrict__ ab,
                    const float* __restrict__ atc, float t) {
    extern __shared__ float sm[];
    float* sP0 = sm;
    float* sP1 = sm + PLANE;
    float* sP2 = sm + 2 * PLANE;
    int tid = threadIdx.x, b = blockIdx.x, h0 = blockIdx.y * 16;
    stage_u_x(sP0, u, b, h0);
    stage_coeff_x(sP2, ab, atc, h0, t, 0.0005f);
    __syncthreads();
    thomas_line(sP0, sP1, sP2, tid * PITCH, 1);
    __syncthreads();
    store_u_x(sP0, u, b, h0);
}

// y full step: block per (b, c) plane, thread-per-column solve along h. In place.
__global__ void k_y(float* __restrict__ u,
                    const float* __restrict__ bb,
                    const float* __restrict__ btc, float t) {
    extern __shared__ float sm[];
    float* sP0 = sm;
    float* sP1 = sm + PLANE;
    float* sP2 = sm + 2 * PLANE;
    int tid = threadIdx.x, b = blockIdx.x, c = blockIdx.y;
    int base = (b * C_DIM + c) * S_DIM * S_DIM;
    for (int idx = tid; idx < S_DIM * S_DIM; idx += NTHREADS) {
        int h = idx >> 7, w = idx & 127;
        sP0[h * PITCH + w] = u[base + idx];
        float v = fmaf(btc[c * S_DIM * S_DIM + idx], t,
                       bb[c * S_DIM * S_DIM + idx]);
        v = fminf(fmaxf(v, EPSF), 10.0f);
        sP2[h * PITCH + w] = v * 0.001f;  // DT/DY^2
    }
    __syncthreads();
    thomas_line(sP0, sP1, sP2, tid, PITCH);  // column solve, conflict-free
    __syncthreads();
    for (int idx = tid; idx < S_DIM * S_DIM; idx += NTHREADS) {
        int h = idx >> 7, w = idx & 127;
        u[base + idx] = sP0[h * PITCH + w];
    }
}

// ---------------- Launch ----------------

extern "C" void kernel_launch(void* const* d_in, const int* in_sizes, int n_in,
                              void* d_out, int out_size) {
    const float* u = (const float*)d_in[0];
    const float* ab = (const float*)d_in[1];
    const float* bb = (const float*)d_in[2];
    const float* atc = (const float*)d_in[3];
    const float* btc = (const float*)d_in[4];
    const float* M = (const float*)d_in[5];
    float* out = (float*)d_out;

    const size_t shmem = (size_t)(3 * PLANE + 64) * sizeof(float);  // ~198.4 KB
    cudaFuncSetAttribute(k_mix_x, cudaFuncAttributeMaxDynamicSharedMemorySize,
                         (int)shmem);
    cudaFuncSetAttribute(k_x_mix_x, cudaFuncAttributeMaxDynamicSharedMemorySize,
                         (int)shmem);
    cudaFuncSetAttribute(k_x, cudaFuncAttributeMaxDynamicSharedMemorySize,
                         (int)shmem);
    cudaFuncSetAttribute(k_y, cudaFuncAttributeMaxDynamicSharedMemorySize,
                         (int)shmem);

    dim3 gx(B_DIM, S_DIM / 16);  // (16, 8) -> 128 blocks
    dim3 gy(B_DIM, C_DIM);       // (16, 8) -> 128 blocks

    const double DTd = 0.001, halfd = 0.0005;

    // step 0: mix + x-half at t=0 (reads input, writes out)
    k_mix_x<<<gx, NTHREADS, shmem>>>(u, M, ab, atc, out, 0.0f);
    for (int k = 0; k < 10; k++) {
        // y full step at t = k*dt + dt/2
        k_y<<<gy, NTHREADS, shmem>>>(out, bb, btc, (float)(k * DTd + halfd));
        if (k < 9) {
            // trailing x of step k + mix + leading x of step k+1,
            // both with alpha at t = (k+1)*dt
            k_x_mix_x<<<gx, NTHREADS, shmem>>>(out, M, ab, atc,
                                               (float)((k + 1) * DTd));
        }
    }
    // trailing x of final step, alpha at t = 10*dt
    k_x<<<gx, NTHREADS, shmem>>>(out, ab, atc, (float)(10 * DTd));
}

// round 4
// speedup vs baseline: 3.2746x; 3.2746x over previous
#include <cuda_runtime.h>

// ADI diffusion, warp-per-line chunked-Thomas + warp-PCR solver.
// B=16, C=8, S=128. 10 steps of [mix, x-half, y-full, x-half].
//
// The reference's (denom + EPS) Thomas is exactly standard Thomas on the
// tridiagonal system with diagonal b + 1e-6. We solve that same system with a
// warp-parallel hybrid: each lane owns 4 contiguous unknowns, locally
// eliminates them down to one interface equation in x_last(chunk), the 32
// interface equations are solved by register PCR (5 shfl rounds), then
// interiors are recovered. fp32 rounding differs from the sequential sweep at
// the ~1e-7 level (system condition ~1), far under the 1e-3 gate.

#define S_DIM 128
#define C_DIM 8
#define B_DIM 16
#define EPSF 1e-6f
#define FULLMASK 0xffffffffu

// Warp-collective solve of one length-128 line.
// co[4]: per-element coefficient (already scaled); d[4]: rhs in, solution out.
// Lane owns global elements i = 4*lane + r, r=0..3.
__device__ __forceinline__ void warp_tridiag(const float co[4], float d[4],
                                             int lane) {
    float bv[4], av[4], cv[4];
#pragma unroll
    for (int r = 0; r < 4; r++) {
        int i = lane * 4 + r;
        float cr = co[r];
        float bb = (i == 0 || i == S_DIM - 1) ? (1.0f + cr) : (1.0f + 2.0f * cr);
        bv[r] = bb + EPSF;
        av[r] = (i == 0) ? 0.0f : -cr;
        cv[r] = (i == S_DIM - 1) ? 0.0f : -cr;
    }
    // Phase 1: forward elimination within chunk.
    //  eq_r: ah_r * x_prev + bh_r * x_r + cv_r * x_{r+1} = dh_r
    float ah[4], bh[4], dh[4], binv[4];
    ah[0] = av[0]; bh[0] = bv[0]; dh[0] = d[0];
    binv[0] = __fdividef(1.0f, bh[0]);
#pragma unroll
    for (int r = 1; r < 4; r++) {
        float k = av[r] * binv[r - 1];
        bh[r] = fmaf(-cv[r - 1], k, bv[r]);
        dh[r] = fmaf(-dh[r - 1], k, d[r]);
        ah[r] = -ah[r - 1] * k;
        binv[r] = __fdividef(1.0f, bh[r]);
    }
    // Phase 2: express x_r = e_r - at_r * x_prev - f_r * x_last for r=0..2.
    float e[3], at[3], f[3];
    e[2] = dh[2] * binv[2];
    at[2] = ah[2] * binv[2];
    f[2] = cv[2] * binv[2];
#pragma unroll
    for (int r = 1; r >= 0; r--) {
        e[r] = fmaf(-cv[r], e[r + 1], dh[r]) * binv[r];
        at[r] = fmaf(-cv[r], at[r + 1], ah[r]) * binv[r];
        f[r] = -cv[r] * f[r + 1] * binv[r];
    }
    // Reduced interface equation in z_j = x_last(chunk j):
    //  A z_{j-1} + B z_j + C z_{j+1} = D
    // using next chunk's x_first = e0' - at0' z_j - f0' z_{j+1}.
    float en = __shfl_down_sync(FULLMASK, e[0], 1);
    float an = __shfl_down_sync(FULLMASK, at[0], 1);
    float fn = __shfl_down_sync(FULLMASK, f[0], 1);
    float A = ah[3];
    float B = fmaf(-cv[3], an, bh[3]);   // lane 31: cv[3]=0 -> neighbor vanishes
    float C = -cv[3] * fn;
    float D = fmaf(-cv[3], en, dh[3]);
    // PCR on the 32-row interface system (5 rounds).
    float Bi = __fdividef(1.0f, B);
#pragma unroll
    for (int s = 1; s < 32; s <<= 1) {
        float Am = __shfl_up_sync(FULLMASK, A, s);
        float Cm = __shfl_up_sync(FULLMASK, C, s);
        float Dm = __shfl_up_sync(FULLMASK, D, s);
        float Bim = __shfl_up_sync(FULLMASK, Bi, s);
        float Ap = __shfl_down_sync(FULLMASK, A, s);
        float Cp = __shfl_down_sync(FULLMASK, C, s);
        float Dp = __shfl_down_sync(FULLMASK, D, s);
        float Bip = __shfl_down_sync(FULLMASK, Bi, s);
        if (lane < s) { Am = 0.0f; Cm = 0.0f; Dm = 0.0f; Bim = 1.0f; }
        if (lane >= 32 - s) { Ap = 0.0f; Cp = 0.0f; Dp = 0.0f; Bip = 1.0f; }
        float k1 = A * Bim;
        float k2 = C * Bip;
        A = -Am * k1;
        C = -Cp * k2;
        B = B - Cm * k1 - Ap * k2;
        D = D - Dm * k1 - Dp * k2;
        Bi = __fdividef(1.0f, B);
    }
    float z = D * Bi;                              // x_last of this chunk
    float zp = __shfl_up_sync(FULLMASK, z, 1);     // x_last of prev (lane0: at==0)
    d[3] = z;
#pragma unroll
    for (int r = 2; r >= 0; r--)
        d[r] = e[r] - at[r] * zp - f[r] * z;
}

__device__ __forceinline__ void load_row4(float v[4], const float* __restrict__ g,
                                          int rowbase, int lane) {
    float4 t = *reinterpret_cast<const float4*>(g + rowbase + 4 * lane);
    v[0] = t.x; v[1] = t.y; v[2] = t.z; v[3] = t.w;
}

__device__ __forceinline__ void store_row4(const float v[4], float* __restrict__ g,
                                           int rowbase, int lane) {
    float4 t; t.x = v[0]; t.y = v[1]; t.z = v[2]; t.w = v[3];
    *reinterpret_cast<float4*>(g + rowbase + 4 * lane) = t;
}

__device__ __forceinline__ void load_coeff_x(float co[4],
                                             const float* __restrict__ cb,
                                             const float* __restrict__ ct,
                                             int crowbase, int lane, float t,
                                             float scale) {
    float4 b4 = *reinterpret_cast<const float4*>(cb + crowbase + 4 * lane);
    float4 t4 = *reinterpret_cast<const float4*>(ct + crowbase + 4 * lane);
    float bb[4] = {b4.x, b4.y, b4.z, b4.w};
    float tt[4] = {t4.x, t4.y, t4.z, t4.w};
#pragma unroll
    for (int r = 0; r < 4; r++) {
        float v = fmaf(tt[r], t, bb[r]);
        v = fminf(fmaxf(v, EPSF), 10.0f);
        co[r] = v * scale;
    }
}

// ---------------- x-direction kernels ----------------
// Block: (b, h-tile of 2 rows) x all 8 channels. 16 warps, warp w -> line
// (c = w>>1, hh = w&1). Lane owns w-elements 4*lane..4*lane+3 (contiguous).
#define XPITCH 132

// mix(channel) then x half-step. Reads u_in, writes u_out.
__global__ void __launch_bounds__(512) k_mix_x(
    const float* __restrict__ u_in, const float* __restrict__ M,
    const float* __restrict__ ab, const float* __restrict__ atc,
    float* __restrict__ u_out, float t) {
    __shared__ __align__(16) float sx[16 * XPITCH];
    __shared__ float sM[64];
    int tid = threadIdx.x, lane = tid & 31, w = tid >> 5;
    int b = blockIdx.x, h0 = blockIdx.y * 2;
    int c = w >> 1, hh = w & 1, h = h0 + hh;
    if (tid < 64) sM[tid] = M[tid];
    int rowbase = (((b * C_DIM + c) * S_DIM) + h) * S_DIM;
    int crowbase = ((c * S_DIM) + h) * S_DIM;
    float u4[4];
    load_row4(u4, u_in, rowbase, lane);
    *reinterpret_cast<float4*>(&sx[w * XPITCH + 4 * lane]) =
        *reinterpret_cast<const float4*>(u4);
    float co[4];
    load_coeff_x(co, ab, atc, crowbase, lane, t, 0.0005f);
    __syncthreads();
    float d[4] = {0.0f, 0.0f, 0.0f, 0.0f};
#pragma unroll
    for (int cc = 0; cc < 8; cc++) {
        float m = sM[c * 8 + cc];
        float4 s4 = *reinterpret_cast<const float4*>(
            &sx[(cc * 2 + hh) * XPITCH + 4 * lane]);
        d[0] = fmaf(m, s4.x, d[0]);
        d[1] = fmaf(m, s4.y, d[1]);
        d[2] = fmaf(m, s4.z, d[2]);
        d[3] = fmaf(m, s4.w, d[3]);
    }
    warp_tridiag(co, d, lane);
    store_row4(d, u_out, rowbase, lane);
}

// trailing x half-step + mix + leading x half-step (same alpha t). In place.
__global__ void __launch_bounds__(512) k_x_mix_x(
    float* __restrict__ u, const float* __restrict__ M,
    const float* __restrict__ ab, const float* __restrict__ atc, float t) {
    __shared__ __align__(16) float sx[16 * XPITCH];
    __shared__ float sM[64];
    int tid = threadIdx.x, lane = tid & 31, w = tid >> 5;
    int b = blockIdx.x, h0 = blockIdx.y * 2;
    int c = w >> 1, hh = w & 1, h = h0 + hh;
    if (tid < 64) sM[tid] = M[tid];
    int rowbase = (((b * C_DIM + c) * S_DIM) + h) * S_DIM;
    int crowbase = ((c * S_DIM) + h) * S_DIM;
    float d[4], co[4];
    load_row4(d, u, rowbase, lane);
    load_coeff_x(co, ab, atc, crowbase, lane, t, 0.0005f);
    warp_tridiag(co, d, lane);  // trailing x of step k
    *reinterpret_cast<float4*>(&sx[w * XPITCH + 4 * lane]) =
        *reinterpret_cast<const float4*>(d);
    __syncthreads();
    float d2[4] = {0.0f, 0.0f, 0.0f, 0.0f};
#pragma unroll
    for (int cc = 0; cc < 8; cc++) {
        float m = sM[c * 8 + cc];
        float4 s4 = *reinterpret_cast<const float4*>(
            &sx[(cc * 2 + hh) * XPITCH + 4 * lane]);
        d2[0] = fmaf(m, s4.x, d2[0]);
        d2[1] = fmaf(m, s4.y, d2[1]);
        d2[2] = fmaf(m, s4.z, d2[2]);
        d2[3] = fmaf(m, s4.w, d2[3]);
    }
    warp_tridiag(co, d2, lane);  // leading x of step k+1
    store_row4(d2, u, rowbase, lane);
}

// final trailing x half-step. In place.
__global__ void __launch_bounds__(512) k_x(
    float* __restrict__ u, const float* __restrict__ ab,
    const float* __restrict__ atc, float t) {
    int tid = threadIdx.x, lane = tid & 31, w = tid >> 5;
    int b = blockIdx.x, h0 = blockIdx.y * 2;
    int c = w >> 1, hh = w & 1, h = h0 + hh;
    int rowbase = (((b * C_DIM + c) * S_DIM) + h) * S_DIM;
    int crowbase = ((c * S_DIM) + h) * S_DIM;
    float d[4], co[4];
    load_row4(d, u, rowbase, lane);
    load_coeff_x(co, ab, atc, crowbase, lane, t, 0.0005f);
    warp_tridiag(co, d, lane);
    store_row4(d, u, rowbase, lane);
}

// ---------------- y-direction kernel ----------------
// Block: (b, c, 16-column tile). 16 warps, warp = one column; smem transpose
// with pitch 132 (float4-aligned, conflict-free staging). In place.
#define YPITCH 132

__global__ void __launch_bounds__(512) k_y(
    float* __restrict__ u, const float* __restrict__ bb,
    const float* __restrict__ btc, float t) {
    __shared__ __align__(16) float sU[16 * YPITCH];
    __shared__ __align__(16) float sC[16 * YPITCH];
    int tid = threadIdx.x, lane = tid & 31, wrp = tid >> 5;
    int b = blockIdx.x, c = blockIdx.y, w0 = blockIdx.z * 16;
    int base = (b * C_DIM + c) * S_DIM * S_DIM;
    int cbase = c * S_DIM * S_DIM;
#pragma unroll
    for (int k = 0; k < 4; k++) {
        int idx = tid + k * 512;          // 2048 elements: (h, wi)
        int h = idx >> 4, wi = idx & 15;
        int g = h * S_DIM + w0 + wi;
        sU[wi * YPITCH + h] = u[base + g];
        float v = fmaf(btc[cbase + g], t, bb[cbase + g]);
        v = fminf(fmaxf(v, EPSF), 10.0f);
        sC[wi * YPITCH + h] = v * 0.001f;  // DT/DY^2
    }
    __syncthreads();
    float d[4], co[4];
    {
        float4 t4 = *reinterpret_cast<const float4*>(&sU[wrp * YPITCH + 4 * lane]);
        d[0] = t4.x; d[1] = t4.y; d[2] = t4.z; d[3] = t4.w;
        float4 c4 = *reinterpret_cast<const float4*>(&sC[wrp * YPITCH + 4 * lane]);
        co[0] = c4.x; co[1] = c4.y; co[2] = c4.z; co[3] = c4.w;
    }
    warp_tridiag(co, d, lane);
    *reinterpret_cast<float4*>(&sU[wrp * YPITCH + 4 * lane]) =
        *reinterpret_cast<const float4*>(d);
    __syncthreads();
#pragma unroll
    for (int k = 0; k < 4; k++) {
        int idx = tid + k * 512;
        int h = idx >> 4, wi = idx & 15;
        u[base + h * S_DIM + w0 + wi] = sU[wi * YPITCH + h];
    }
}

// ---------------- Launch ----------------

extern "C" void kernel_launch(void* const* d_in, const int* in_sizes, int n_in,
                              void* d_out, int out_size) {
    const float* u = (const float*)d_in[0];
    const float* ab = (const float*)d_in[1];
    const float* bb = (const float*)d_in[2];
    const float* atc = (const float*)d_in[3];
    const float* btc = (const float*)d_in[4];
    const float* M = (const float*)d_in[5];
    float* out = (float*)d_out;

    dim3 gx(B_DIM, S_DIM / 2);       // 16 x 64 = 1024 blocks
    dim3 gy(B_DIM, C_DIM, S_DIM / 16);  // 16 x 8 x 8 = 1024 blocks

    const double DTd = 0.001, halfd = 0.0005;

    k_mix_x<<<gx, 512>>>(u, M, ab, atc, out, 0.0f);
    for (int k = 0; k < 10; k++) {
        k_y<<<gy, 512>>>(out, bb, btc, (float)(k * DTd + halfd));
        if (k < 9)
            k_x_mix_x<<<gx, 512>>>(out, M, ab, atc, (float)((k + 1) * DTd));
    }
    k_x<<<gx, 512>>>(out, ab, atc, (float)(10 * DTd));
}

// round 5
// speedup vs baseline: 5.9719x; 1.8237x over previous
#include <cuda_runtime.h>

// ADI diffusion, warp-per-line Neumann-series tridiagonal solve.
// B=16, C=8, S=128. 10 steps of [mix, x-half, y-full, x-half].
//
// The reference's (denom + EPS) Thomas is exactly standard Thomas on the
// tridiagonal system with diagonal b + 1e-6. That system is near-identity:
// off-diag/diag ratio r = co/(1+2co) ~ 5e-4..1e-3 for these inputs
// (coeff = clip(~1, eps, 10) * dt/(2 dx^2)). We solve with a truncated
// Neumann series x = (I + N + N^2 + N^3) B^-1 d, N = -B^-1 A_off,
// truncation error ||N^4|| ~ 2e-11 per sweep (1e-8 even at the clip
// ceiling), vastly below the 1e-3 gate.

#define S_DIM 128
#define C_DIM 8
#define B_DIM 16
#define EPSF 1e-6f
#define FULLMASK 0xffffffffu

// Warp-collective approximate solve of one length-128 line.
// co[4]: per-element coefficient (already scaled); d[4]: rhs in, solution out.
// Lane owns global elements i = 4*lane + r, r=0..3 (contiguous).
__device__ __forceinline__ void neumann_line(const float co[4], float d[4],
                                             int lane) {
    float w[4], y[4], acc[4];
#pragma unroll
    for (int r = 0; r < 4; r++) {
        int i = lane * 4 + r;
        float cr = co[r];
        float b = (i == 0 || i == S_DIM - 1) ? (1.0f + cr) : (1.0f + 2.0f * cr);
        b += EPSF;
        float g = __fdividef(1.0f, b);
        w[r] = cr * g;       // off-diagonal weight (both neighbors symmetric)
        y[r] = d[r] * g;     // y0 = B^-1 d
        acc[r] = y[r];
    }
#pragma unroll
    for (int k = 0; k < 3; k++) {
        float up = __shfl_up_sync(FULLMASK, y[3], 1);    // prev lane's last
        float dn = __shfl_down_sync(FULLMASK, y[0], 1);  // next lane's first
        if (lane == 0) up = 0.0f;    // i=0 has no left neighbor
        if (lane == 31) dn = 0.0f;   // i=127 has no right neighbor
        float n0 = w[0] * (up + y[1]);
        float n1 = w[1] * (y[0] + y[2]);
        float n2 = w[2] * (y[1] + y[3]);
        float n3 = w[3] * (y[2] + dn);
        y[0] = n0; y[1] = n1; y[2] = n2; y[3] = n3;
        acc[0] += n0; acc[1] += n1; acc[2] += n2; acc[3] += n3;
    }
#pragma unroll
    for (int r = 0; r < 4; r++) d[r] = acc[r];
}

__device__ __forceinline__ void load_row4(float v[4], const float* __restrict__ g,
                                          int rowbase, int lane) {
    float4 t = *reinterpret_cast<const float4*>(g + rowbase + 4 * lane);
    v[0] = t.x; v[1] = t.y; v[2] = t.z; v[3] = t.w;
}

__device__ __forceinline__ void store_row4(const float v[4], float* __restrict__ g,
                                           int rowbase, int lane) {
    float4 t; t.x = v[0]; t.y = v[1]; t.z = v[2]; t.w = v[3];
    *reinterpret_cast<float4*>(g + rowbase + 4 * lane) = t;
}

__device__ __forceinline__ void load_coeff_x(float co[4],
                                             const float* __restrict__ cb,
                                             const float* __restrict__ ct,
                                             int crowbase, int lane, float t,
                                             float scale) {
    float4 b4 = *reinterpret_cast<const float4*>(cb + crowbase + 4 * lane);
    float4 t4 = *reinterpret_cast<const float4*>(ct + crowbase + 4 * lane);
    float bb[4] = {b4.x, b4.y, b4.z, b4.w};
    float tt[4] = {t4.x, t4.y, t4.z, t4.w};
#pragma unroll
    for (int r = 0; r < 4; r++) {
        float v = fmaf(tt[r], t, bb[r]);
        v = fminf(fmaxf(v, EPSF), 10.0f);
        co[r] = v * scale;
    }
}

// ---------------- x-direction kernels ----------------
// Block: (b, h-tile of 2 rows) x all 8 channels. 16 warps, warp w -> line
// (c = w>>1, hh = w&1). Lane owns w-elements 4*lane..4*lane+3 (contiguous).
#define XPITCH 132

// mix(channel) then x half-step. Reads u_in, writes u_out.
__global__ void __launch_bounds__(512) k_mix_x(
    const float* __restrict__ u_in, const float* __restrict__ M,
    const float* __restrict__ ab, const float* __restrict__ atc,
    float* __restrict__ u_out, float t) {
    __shared__ __align__(16) float sx[16 * XPITCH];
    __shared__ float sM[64];
    int tid = threadIdx.x, lane = tid & 31, w = tid >> 5;
    int b = blockIdx.x, h0 = blockIdx.y * 2;
    int c = w >> 1, hh = w & 1, h = h0 + hh;
    if (tid < 64) sM[tid] = M[tid];
    int rowbase = (((b * C_DIM + c) * S_DIM) + h) * S_DIM;
    int crowbase = ((c * S_DIM) + h) * S_DIM;
    float u4[4];
    load_row4(u4, u_in, rowbase, lane);
    *reinterpret_cast<float4*>(&sx[w * XPITCH + 4 * lane]) =
        *reinterpret_cast<const float4*>(u4);
    float co[4];
    load_coeff_x(co, ab, atc, crowbase, lane, t, 0.0005f);
    __syncthreads();
    float d[4] = {0.0f, 0.0f, 0.0f, 0.0f};
#pragma unroll
    for (int cc = 0; cc < 8; cc++) {
        float m = sM[c * 8 + cc];
        float4 s4 = *reinterpret_cast<const float4*>(
            &sx[(cc * 2 + hh) * XPITCH + 4 * lane]);
        d[0] = fmaf(m, s4.x, d[0]);
        d[1] = fmaf(m, s4.y, d[1]);
        d[2] = fmaf(m, s4.z, d[2]);
        d[3] = fmaf(m, s4.w, d[3]);
    }
    neumann_line(co, d, lane);
    store_row4(d, u_out, rowbase, lane);
}

// trailing x half-step + mix + leading x half-step (same alpha t). In place.
__global__ void __launch_bounds__(512) k_x_mix_x(
    float* __restrict__ u, const float* __restrict__ M,
    const float* __restrict__ ab, const float* __restrict__ atc, float t) {
    __shared__ __align__(16) float sx[16 * XPITCH];
    __shared__ float sM[64];
    int tid = threadIdx.x, lane = tid & 31, w = tid >> 5;
    int b = blockIdx.x, h0 = blockIdx.y * 2;
    int c = w >> 1, hh = w & 1, h = h0 + hh;
    if (tid < 64) sM[tid] = M[tid];
    int rowbase = (((b * C_DIM + c) * S_DIM) + h) * S_DIM;
    int crowbase = ((c * S_DIM) + h) * S_DIM;
    float d[4], co[4];
    load_row4(d, u, rowbase, lane);
    load_coeff_x(co, ab, atc, crowbase, lane, t, 0.0005f);
    neumann_line(co, d, lane);  // trailing x of step k
    *reinterpret_cast<float4*>(&sx[w * XPITCH + 4 * lane]) =
        *reinterpret_cast<const float4*>(d);
    __syncthreads();
    float d2[4] = {0.0f, 0.0f, 0.0f, 0.0f};
#pragma unroll
    for (int cc = 0; cc < 8; cc++) {
        float m = sM[c * 8 + cc];
        float4 s4 = *reinterpret_cast<const float4*>(
            &sx[(cc * 2 + hh) * XPITCH + 4 * lane]);
        d2[0] = fmaf(m, s4.x, d2[0]);
        d2[1] = fmaf(m, s4.y, d2[1]);
        d2[2] = fmaf(m, s4.z, d2[2]);
        d2[3] = fmaf(m, s4.w, d2[3]);
    }
    neumann_line(co, d2, lane);  // leading x of step k+1
    store_row4(d2, u, rowbase, lane);
}

// final trailing x half-step. In place.
__global__ void __launch_bounds__(512) k_x(
    float* __restrict__ u, const float* __restrict__ ab,
    const float* __restrict__ atc, float t) {
    int tid = threadIdx.x, lane = tid & 31, w = tid >> 5;
    int b = blockIdx.x, h0 = blockIdx.y * 2;
    int c = w >> 1, hh = w & 1, h = h0 + hh;
    int rowbase = (((b * C_DIM + c) * S_DIM) + h) * S_DIM;
    int crowbase = ((c * S_DIM) + h) * S_DIM;
    float d[4], co[4];
    load_row4(d, u, rowbase, lane);
    load_coeff_x(co, ab, atc, crowbase, lane, t, 0.0005f);
    neumann_line(co, d, lane);
    store_row4(d, u, rowbase, lane);
}

// ---------------- y-direction kernel ----------------
// Block: (b, c, 16-column tile). 16 warps, warp = one column; smem transpose
// with pitch 132 (float4-aligned, conflict-free staging). In place.
#define YPITCH 132

__global__ void __launch_bounds__(512) k_y(
    float* __restrict__ u, const float* __restrict__ bb,
    const float* __restrict__ btc, float t) {
    __shared__ __align__(16) float sU[16 * YPITCH];
    __shared__ __align__(16) float sC[16 * YPITCH];
    int tid = threadIdx.x, lane = tid & 31, wrp = tid >> 5;
    int b = blockIdx.x, c = blockIdx.y, w0 = blockIdx.z * 16;
    int base = (b * C_DIM + c) * S_DIM * S_DIM;
    int cbase = c * S_DIM * S_DIM;
#pragma unroll
    for (int k = 0; k < 4; k++) {
        int idx = tid + k * 512;          // 2048 elements: (h, wi)
        int h = idx >> 4, wi = idx & 15;
        int g = h * S_DIM + w0 + wi;
        sU[wi * YPITCH + h] = u[base + g];
        float v = fmaf(btc[cbase + g], t, bb[cbase + g]);
        v = fminf(fmaxf(v, EPSF), 10.0f);
        sC[wi * YPITCH + h] = v * 0.001f;  // DT/DY^2
    }
    __syncthreads();
    float d[4], co[4];
    {
        float4 t4 = *reinterpret_cast<const float4*>(&sU[wrp * YPITCH + 4 * lane]);
        d[0] = t4.x; d[1] = t4.y; d[2] = t4.z; d[3] = t4.w;
        float4 c4 = *reinterpret_cast<const float4*>(&sC[wrp * YPITCH + 4 * lane]);
        co[0] = c4.x; co[1] = c4.y; co[2] = c4.z; co[3] = c4.w;
    }
    neumann_line(co, d, lane);
    *reinterpret_cast<float4*>(&sU[wrp * YPITCH + 4 * lane]) =
        *reinterpret_cast<const float4*>(d);
    __syncthreads();
#pragma unroll
    for (int k = 0; k < 4; k++) {
        int idx = tid + k * 512;
        int h = idx >> 4, wi = idx & 15;
        u[base + h * S_DIM + w0 + wi] = sU[wi * YPITCH + h];
    }
}

// ---------------- Launch ----------------

extern "C" void kernel_launch(void* const* d_in, const int* in_sizes, int n_in,
                              void* d_out, int out_size) {
    const float* u = (const float*)d_in[0];
    const float* ab = (const float*)d_in[1];
    const float* bb = (const float*)d_in[2];
    const float* atc = (const float*)d_in[3];
    const float* btc = (const float*)d_in[4];
    const float* M = (const float*)d_in[5];
    float* out = (float*)d_out;

    dim3 gx(B_DIM, S_DIM / 2);          // 16 x 64 = 1024 blocks
    dim3 gy(B_DIM, C_DIM, S_DIM / 16);  // 16 x 8 x 8 = 1024 blocks

    const double DTd = 0.001, halfd = 0.0005;

    k_mix_x<<<gx, 512>>>(u, M, ab, atc, out, 0.0f);
    for (int k = 0; k < 10; k++) {
        k_y<<<gy, 512>>>(out, bb, btc, (float)(k * DTd + halfd));
        if (k < 9)
            k_x_mix_x<<<gx, 512>>>(out, M, ab, atc, (float)((k + 1) * DTd));
    }
    k_x<<<gx, 512>>>(out, ab, atc, (float)(10 * DTd));
}

// round 7
// speedup vs baseline: 6.4114x; 1.0736x over previous
#include <cuda_runtime.h>

// ADI diffusion, Neumann-series tridiagonal solves.
// B=16, C=8, S=128. 10 steps of [mix, x-half, y-full, x-half].
//
// The reference's (denom + EPS) Thomas is standard Thomas on the tridiagonal
// system with diagonal b + 1e-6. That system is near-identity (off-diag/diag
// ratio ~5e-4..1e-3), so x = (I + N + N^2 + N^3) B^-1 d with N = -B^-1 A_off
// is exact to ~1e-11 per sweep.
//
// x sweeps: warp-per-row, lane owns 4 contiguous w, neighbor exchange by shfl.
// y sweep: radius-1 Jacobi stencil applied 3x along h in shared memory,
//          block = (b, c, 32-col slab), float4-vectorized along w, no transpose.

#define S_DIM 128
#define C_DIM 8
#define B_DIM 16
#define EPSF 1e-6f
#define FULLMASK 0xffffffffu

// ---------------- warp Neumann solve (x direction) ----------------
__device__ __forceinline__ void neumann_line(const float co[4], float d[4],
                                             int lane) {
    float w[4], y[4], acc[4];
#pragma unroll
    for (int r = 0; r < 4; r++) {
        int i = lane * 4 + r;
        float cr = co[r];
        float b = (i == 0 || i == S_DIM - 1) ? (1.0f + cr) : (1.0f + 2.0f * cr);
        b += EPSF;
        float g = __fdividef(1.0f, b);
        w[r] = cr * g;
        y[r] = d[r] * g;
        acc[r] = y[r];
    }
#pragma unroll
    for (int k = 0; k < 3; k++) {
        float up = __shfl_up_sync(FULLMASK, y[3], 1);
        float dn = __shfl_down_sync(FULLMASK, y[0], 1);
        if (lane == 0) up = 0.0f;
        if (lane == 31) dn = 0.0f;
        float n0 = w[0] * (up + y[1]);
        float n1 = w[1] * (y[0] + y[2]);
        float n2 = w[2] * (y[1] + y[3]);
        float n3 = w[3] * (y[2] + dn);
        y[0] = n0; y[1] = n1; y[2] = n2; y[3] = n3;
        acc[0] += n0; acc[1] += n1; acc[2] += n2; acc[3] += n3;
    }
#pragma unroll
    for (int r = 0; r < 4; r++) d[r] = acc[r];
}

__device__ __forceinline__ void load_row4(float v[4], const float* __restrict__ g,
                                          int rowbase, int lane) {
    float4 t = *reinterpret_cast<const float4*>(g + rowbase + 4 * lane);
    v[0] = t.x; v[1] = t.y; v[2] = t.z; v[3] = t.w;
}

__device__ __forceinline__ void store_row4(const float v[4], float* __restrict__ g,
                                           int rowbase, int lane) {
    float4 t; t.x = v[0]; t.y = v[1]; t.z = v[2]; t.w = v[3];
    *reinterpret_cast<float4*>(g + rowbase + 4 * lane) = t;
}

__device__ __forceinline__ void load_coeff_x(float co[4],
                                             const float* __restrict__ cb,
                                             const float* __restrict__ ct,
                                             int crowbase, int lane, float t,
                                             float scale) {
    float4 b4 = *reinterpret_cast<const float4*>(cb + crowbase + 4 * lane);
    float4 t4 = *reinterpret_cast<const float4*>(ct + crowbase + 4 * lane);
    float bb[4] = {b4.x, b4.y, b4.z, b4.w};
    float tt[4] = {t4.x, t4.y, t4.z, t4.w};
#pragma unroll
    for (int r = 0; r < 4; r++) {
        float v = fmaf(tt[r], t, bb[r]);
        v = fminf(fmaxf(v, EPSF), 10.0f);
        co[r] = v * scale;
    }
}

// ---------------- x-direction kernels ----------------
#define XPITCH 132

__global__ void __launch_bounds__(512) k_mix_x(
    const float* __restrict__ u_in, const float* __restrict__ M,
    const float* __restrict__ ab, const float* __restrict__ atc,
    float* __restrict__ u_out, float t) {
    __shared__ __align__(16) float sx[16 * XPITCH];
    __shared__ float sM[64];
    int tid = threadIdx.x, lane = tid & 31, w = tid >> 5;
    int b = blockIdx.x, h0 = blockIdx.y * 2;
    int c = w >> 1, hh = w & 1, h = h0 + hh;
    if (tid < 64) sM[tid] = M[tid];
    int rowbase = (((b * C_DIM + c) * S_DIM) + h) * S_DIM;
    int crowbase = ((c * S_DIM) + h) * S_DIM;
    float u4[4];
    load_row4(u4, u_in, rowbase, lane);
    *reinterpret_cast<float4*>(&sx[w * XPITCH + 4 * lane]) =
        *reinterpret_cast<const float4*>(u4);
    float co[4];
    load_coeff_x(co, ab, atc, crowbase, lane, t, 0.0005f);
    __syncthreads();
    float d[4] = {0.0f, 0.0f, 0.0f, 0.0f};
#pragma unroll
    for (int cc = 0; cc < 8; cc++) {
        float m = sM[c * 8 + cc];
        float4 s4 = *reinterpret_cast<const float4*>(
            &sx[(cc * 2 + hh) * XPITCH + 4 * lane]);
        d[0] = fmaf(m, s4.x, d[0]);
        d[1] = fmaf(m, s4.y, d[1]);
        d[2] = fmaf(m, s4.z, d[2]);
        d[3] = fmaf(m, s4.w, d[3]);
    }
    neumann_line(co, d, lane);
    store_row4(d, u_out, rowbase, lane);
}

__global__ void __launch_bounds__(512) k_x_mix_x(
    float* __restrict__ u, const float* __restrict__ M,
    const float* __restrict__ ab, const float* __restrict__ atc, float t) {
    __shared__ __align__(16) float sx[16 * XPITCH];
    __shared__ float sM[64];
    int tid = threadIdx.x, lane = tid & 31, w = tid >> 5;
    int b = blockIdx.x, h0 = blockIdx.y * 2;
    int c = w >> 1, hh = w & 1, h = h0 + hh;
    if (tid < 64) sM[tid] = M[tid];
    int rowbase = (((b * C_DIM + c) * S_DIM) + h) * S_DIM;
    int crowbase = ((c * S_DIM) + h) * S_DIM;
    float d[4], co[4];
    load_row4(d, u, rowbase, lane);
    load_coeff_x(co, ab, atc, crowbase, lane, t, 0.0005f);
    neumann_line(co, d, lane);
    *reinterpret_cast<float4*>(&sx[w * XPITCH + 4 * lane]) =
        *reinterpret_cast<const float4*>(d);
    __syncthreads();
    float d2[4] = {0.0f, 0.0f, 0.0f, 0.0f};
#pragma unroll
    for (int cc = 0; cc < 8; cc++) {
        float m = sM[c * 8 + cc];
        float4 s4 = *reinterpret_cast<const float4*>(
            &sx[(cc * 2 + hh) * XPITCH + 4 * lane]);
        d2[0] = fmaf(m, s4.x, d2[0]);
        d2[1] = fmaf(m, s4.y, d2[1]);
        d2[2] = fmaf(m, s4.z, d2[2]);
        d2[3] = fmaf(m, s4.w, d2[3]);
    }
    neumann_line(co, d2, lane);
    store_row4(d2, u, rowbase, lane);
}

__global__ void __launch_bounds__(512) k_x(
    float* __restrict__ u, const float* __restrict__ ab,
    const float* __restrict__ atc, float t) {
    int tid = threadIdx.x, lane = tid & 31, w = tid >> 5;
    int b = blockIdx.x, h0 = blockIdx.y * 2;
    int c = w >> 1, hh = w & 1, h = h0 + hh;
    int rowbase = (((b * C_DIM + c) * S_DIM) + h) * S_DIM;
    int crowbase = ((c * S_DIM) + h) * S_DIM;
    float d[4], co[4];
    load_row4(d, u, rowbase, lane);
    load_coeff_x(co, ab, atc, crowbase, lane, t, 0.0005f);
    neumann_line(co, d, lane);
    store_row4(d, u, rowbase, lane);
}

// ---------------- y-direction kernel (stencil, no transpose) ----------------
// Block = (b, c, 32-column slab). 512 threads. Each thread owns 2 float4
// elements e and e+512 of the 1024-float4 tile (h = e>>3, colgroup g = e&7).
// y_{k+1}[h] = w[h] * (y_k[h-1] + y_k[h+1]); acc = y0+y1+y2+y3.
// Weights w stay in registers; y ping-pongs between two 16KB smem buffers.

__global__ void __launch_bounds__(512) k_y(
    float* __restrict__ u, const float* __restrict__ bb,
    const float* __restrict__ btc, float t) {
    __shared__ __align__(16) float4 sA[1024];
    __shared__ __align__(16) float4 sB[1024];
    int tid = threadIdx.x;
    int b = blockIdx.x, c = blockIdx.y, w0 = blockIdx.z * 32;
    const float4* __restrict__ uP = reinterpret_cast<const float4*>(
        u + (b * C_DIM + c) * S_DIM * S_DIM + w0);
    const float4* __restrict__ bbP = reinterpret_cast<const float4*>(
        bb + c * S_DIM * S_DIM + w0);
    const float4* __restrict__ btP = reinterpret_cast<const float4*>(
        btc + c * S_DIM * S_DIM + w0);
    // global float4 index for tile element e: (h = e>>3) row has 32 float4s,
    // we take groups 0..7 at offset h*32 + g.
    float4 wgt[2], acc[2];
#pragma unroll
    for (int k = 0; k < 2; k++) {
        int e = tid + k * 512;
        int h = e >> 3, g = e & 7;
        int gidx = h * 32 + g;
        float4 u4 = uP[gidx];
        float4 b4 = bbP[gidx];
        float4 t4 = btP[gidx];
        float bd_edge = (h == 0 || h == S_DIM - 1) ? 1.0f : 2.0f;
        float co, bd, inv;
        float4 wv, yv;
        co = fminf(fmaxf(fmaf(t4.x, t, b4.x), EPSF), 10.0f) * 0.001f;
        bd = fmaf(bd_edge, co, 1.0f) + EPSF; inv = __fdividef(1.0f, bd);
        wv.x = co * inv; yv.x = u4.x * inv;
        co = fminf(fmaxf(fmaf(t4.y, t, b4.y), EPSF), 10.0f) * 0.001f;
        bd = fmaf(bd_edge, co, 1.0f) + EPSF; inv = __fdividef(1.0f, bd);
        wv.y = co * inv; yv.y = u4.y * inv;
        co = fminf(fmaxf(fmaf(t4.z, t, b4.z), EPSF), 10.0f) * 0.001f;
        bd = fmaf(bd_edge, co, 1.0f) + EPSF; inv = __fdividef(1.0f, bd);
        wv.z = co * inv; yv.z = u4.z * inv;
        co = fminf(fmaxf(fmaf(t4.w, t, b4.w), EPSF), 10.0f) * 0.001f;
        bd = fmaf(bd_edge, co, 1.0f) + EPSF; inv = __fdividef(1.0f, bd);
        wv.w = co * inv; yv.w = u4.w * inv;
        wgt[k] = wv;
        acc[k] = yv;
        sA[e] = yv;
    }
    float4* cur = sA;
    float4* nxt = sB;
#pragma unroll
    for (int it = 0; it < 3; it++) {
        __syncthreads();
        float4 yn[2];
#pragma unroll
        for (int k = 0; k < 2; k++) {
            int e = tid + k * 512;
            int h = e >> 3;
            float4 ym = (h > 0) ? cur[e - 8] : make_float4(0.f, 0.f, 0.f, 0.f);
            float4 yp = (h < S_DIM - 1) ? cur[e + 8]
                                        : make_float4(0.f, 0.f, 0.f, 0.f);
            float4 wv = wgt[k];
            float4 y;
            y.x = wv.x * (ym.x + yp.x);
            y.y = wv.y * (ym.y + yp.y);
            y.z = wv.z * (ym.z + yp.z);
            y.w = wv.w * (ym.w + yp.w);
            acc[k].x += y.x; acc[k].y += y.y;
            acc[k].z += y.z; acc[k].w += y.w;
            yn[k] = y;
        }
        if (it < 2) {
            // write after both reads of this thread are done; other threads'
            // reads of cur are protected because nxt != cur.
#pragma unroll
            for (int k = 0; k < 2; k++) nxt[tid + k * 512] = yn[k];
            float4* tmp = cur; cur = nxt; nxt = tmp;
        }
    }
    float4* __restrict__ uOut = reinterpret_cast<float4*>(
        u + (b * C_DIM + c) * S_DIM * S_DIM + w0);
#pragma unroll
    for (int k = 0; k < 2; k++) {
        int e = tid + k * 512;
        int h = e >> 3, g = e & 7;
        uOut[h * 32 + g] = acc[k];
    }
}

// ---------------- Launch ----------------

extern "C" void kernel_launch(void* const* d_in, const int* in_sizes, int n_in,
                              void* d_out, int out_size) {
    const float* u = (const float*)d_in[0];
    const float* ab = (const float*)d_in[1];
    const float* bb = (const float*)d_in[2];
    const float* atc = (const float*)d_in[3];
    const float* btc = (const float*)d_in[4];
    const float* M = (const float*)d_in[5];
    float* out = (float*)d_out;

    dim3 gx(B_DIM, S_DIM / 2);   // 1024 blocks
    dim3 gy(B_DIM, C_DIM, 4);    // 512 blocks (32-col slabs)

    const double DTd = 0.001, halfd = 0.0005;

    k_mix_x<<<gx, 512>>>(u, M, ab, atc, out, 0.0f);
    for (int k = 0; k < 10; k++) {
        k_y<<<gy, 512>>>(out, bb, btc, (float)(k * DTd + halfd));
        if (k < 9)
            k_x_mix_x<<<gx, 512>>>(out, M, ab, atc, (float)((k + 1) * DTd));
    }
    k_x<<<gx, 512>>>(out, ab, atc, (float)(10 * DTd));
}